// round 14
// baseline (speedup 1.0000x reference)
#include <cuda_runtime.h>
#include <cuda_bf16.h>
#include <math.h>
#include <stdint.h>

typedef unsigned long long u64;
#define DI __device__ __forceinline__

// ---------------- packed f32x2 helpers (FFMA2 only via PTX) ----------------
DI u64 pk2(float x, float y){ u64 r; asm("mov.b64 %0,{%1,%2};" : "=l"(r) : "f"(x), "f"(y)); return r; }
DI void upk2(u64 v, float& x, float& y){ asm("mov.b64 {%0,%1},%2;" : "=f"(x), "=f"(y) : "l"(v)); }
DI u64 ffma2(u64 a, u64 b, u64 c){ u64 d; asm("fma.rn.f32x2 %0,%1,%2,%3;" : "=l"(d) : "l"(a), "l"(b), "l"(c)); return d; }

DI float wsum(float v){
#pragma unroll
  for(int o=16;o;o>>=1) v += __shfl_xor_sync(0xffffffffu, v, o);
  return v;
}

// ---------------- warp-level bf16 HMMA (plain PTX, works on sm_103) --------
DI void mma16816(float* d, const uint32_t* a, const uint32_t* b, const float* c){
  asm volatile("mma.sync.aligned.m16n8k16.row.col.f32.bf16.bf16.f32 "
    "{%0,%1,%2,%3}, {%4,%5,%6,%7}, {%8,%9}, {%10,%11,%12,%13};"
    : "=f"(d[0]),"=f"(d[1]),"=f"(d[2]),"=f"(d[3])
    : "r"(a[0]),"r"(a[1]),"r"(a[2]),"r"(a[3]), "r"(b[0]),"r"(b[1]),
      "f"(c[0]),"f"(c[1]),"f"(c[2]),"f"(c[3]));
}

// Shapes: B=8, H=W=128, N=16384, C=64, heads=1, hd=64, R=8, Nr=256, HID=256

// ---------------- scratch ----------------
__device__ float g_h  [8*16384*64];
__device__ float g_o  [8*16384*64];
__device__ float g_xrp[8*2048*64];
__device__ float g_f  [8*16384*256];
__device__ __nv_bfloat16 g_qb [8*16384*64];  // Q bf16 (pre-scaled 1/8)
__device__ __nv_bfloat16 g_kb [8*256*64];    // K bf16 [b][m][c]
__device__ __nv_bfloat16 g_vtb[8*64*256];    // V^T bf16 [b][c][m]

// =====================================================================
// kA: LN1 + q projection -> bf16 Q. Warp handles 8 rows.
// =====================================================================
__global__ void __launch_bounds__(256) kA(const float* __restrict__ x,
    const float* __restrict__ g1, const float* __restrict__ b1,
    const float* __restrict__ qw, const float* __restrict__ qb){
  __shared__ float qws[64*64];
  __shared__ float hs[8][8*64];
  __shared__ float gs[64], bs[64], qbs[64];
  int t = threadIdx.x;
  for (int i=t;i<4096;i+=256) qws[i]=qw[i];
  if (t<64){ gs[t]=g1[t]; bs[t]=b1[t]; qbs[t]=qb[t]; }
  __syncthreads();
  int w=t>>5, l=t&31;
  float* hw = hs[w];
  float g0=gs[2*l], g1v=gs[2*l+1], b0=bs[2*l], b1v=bs[2*l+1];
  u64 qbp = pk2(qbs[2*l], qbs[2*l+1]);
  for (int task=blockIdx.x; task<2048; task+=1024){
    int base = task*64 + w*8;
#pragma unroll
    for (int i=0;i<8;i++){
      const float2 xv = *(const float2*)(x + (base+i)*64 + 2*l);
      float m  = wsum(xv.x + xv.y) * (1.f/64.f);
      float s2 = wsum(xv.x*xv.x + xv.y*xv.y) * (1.f/64.f);
      float rs = rsqrtf(fmaxf(s2 - m*m, 0.f) + 1e-5f);
      float h0 = (xv.x - m)*rs*g0 + b0;
      float h1 = (xv.y - m)*rs*g1v + b1v;
      *(float2*)(g_h + (base+i)*64 + 2*l) = make_float2(h0, h1);
      hw[i*64 + 2*l] = h0; hw[i*64 + 2*l+1] = h1;
    }
    __syncwarp();
    u64 acc[8];
#pragma unroll
    for (int i=0;i<8;i++) acc[i]=qbp;
#pragma unroll 8
    for (int k=0;k<64;k++){
      const float2 wv = *(const float2*)(qws + k*64 + 2*l);
      u64 wp = pk2(wv.x, wv.y);
#pragma unroll
      for (int i=0;i<8;i++){
        float hv = hw[i*64 + k];
        acc[i] = ffma2(pk2(hv,hv), wp, acc[i]);
      }
    }
#pragma unroll
    for (int i=0;i<8;i++){
      float o0,o1; upk2(acc[i],o0,o1);
      __nv_bfloat162 qq = __floats2bfloat162_rn(o0*0.125f, o1*0.125f);
      *(__nv_bfloat162*)(g_qb + (base+i)*64 + 2*l) = qq;
    }
    __syncwarp();
  }
}

// =====================================================================
// kB: SR conv as GEMM M=2048,K=4096,N=64. grid(64,8), K split by ky.
// =====================================================================
__global__ void __launch_bounds__(256) kB(const float* __restrict__ srw){
  __shared__ float As[32*64];
  __shared__ float Ws[64*64];
  int t = threadIdx.x;
  int m0 = blockIdx.x*32;
  int ky = blockIdx.y;
  int g = t>>5, l = t&31;
  int c2 = l*2;
  int b = m0 >> 8;
  u64 acc[4] = {0,0,0,0};
  for (int kx=0; kx<8; kx++){
    for (int i2=t; i2<1024; i2+=256){
      int r = i2>>5; int ci = (i2&31)*2;
      int mm = (m0 + r) & 255;
      int oy = mm>>4, ox = mm&15;
      const float2 v = *(const float2*)(g_h + ((b*16384) + (oy*8+ky)*128 + (ox*8+kx))*64 + ci);
      *(float2*)(As + r*64 + ci) = v;
    }
    const float* wsl = srw + ((ky*8+kx)*64)*64;
    for (int i2=t; i2<2048; i2+=256)
      *(float2*)(Ws + i2*2) = *(const float2*)(wsl + i2*2);
    __syncthreads();
#pragma unroll 8
    for (int ci=0; ci<64; ci++){
      const float2 w2 = *(const float2*)(Ws + ci*64 + c2);
      u64 wp = pk2(w2.x, w2.y);
#pragma unroll
      for (int j=0;j<4;j++){
        float a = As[(g + 8*j)*64 + ci];
        acc[j] = ffma2(pk2(a,a), wp, acc[j]);
      }
    }
    __syncthreads();
  }
#pragma unroll
  for (int j=0;j<4;j++){
    float o0,o1; upk2(acc[j],o0,o1);
    *(float2*)(g_xrp + ((ky*2048) + m0 + g + 8*j)*64 + c2) = make_float2(o0,o1);
  }
}

// =====================================================================
// kC: sum conv partials + sr_b + LN + kv projection -> bf16 K, V^T.
// =====================================================================
__global__ void __launch_bounds__(256) kC(const float* __restrict__ srb,
    const float* __restrict__ sg, const float* __restrict__ sb,
    const float* __restrict__ kvw, const float* __restrict__ kvb){
  __shared__ float kws[64*128];
  __shared__ float hs[8][64];
  int t = threadIdx.x;
  for (int i=t;i<8192;i+=256) kws[i]=kvw[i];
  __syncthreads();
  int w=t>>5, l=t&31;
  int m = blockIdx.x*8 + w;
  float v0 = srb[2*l], v1 = srb[2*l+1];
#pragma unroll
  for (int p=0;p<8;p++){
    const float2 a = *(const float2*)(g_xrp + (p*2048+m)*64 + 2*l);
    v0 += a.x; v1 += a.y;
  }
  float mn = wsum(v0+v1)*(1.f/64.f);
  float s2 = wsum(v0*v0+v1*v1)*(1.f/64.f);
  float rs = rsqrtf(fmaxf(s2-mn*mn,0.f)+1e-5f);
  float h0 = (v0-mn)*rs*sg[2*l]+sb[2*l];
  float h1 = (v1-mn)*rs*sg[2*l+1]+sb[2*l+1];
  hs[w][2*l]=h0; hs[w][2*l+1]=h1;
  __syncwarp();
  u64 ak = pk2(kvb[2*l], kvb[2*l+1]);
  u64 av = pk2(kvb[64+2*l], kvb[64+2*l+1]);
#pragma unroll 8
  for (int k=0;k<64;k++){
    float hb = hs[w][k];
    u64 hp = pk2(hb,hb);
    const float2 wk = *(const float2*)(kws + k*128 + 2*l);
    const float2 wv = *(const float2*)(kws + k*128 + 64 + 2*l);
    ak = ffma2(hp, pk2(wk.x,wk.y), ak);
    av = ffma2(hp, pk2(wv.x,wv.y), av);
  }
  int b = m>>8, mm = m&255;
  float k0,k1,vv0,vv1; upk2(ak,k0,k1); upk2(av,vv0,vv1);
  *(__nv_bfloat162*)(g_kb + (b*256+mm)*64 + 2*l) = __floats2bfloat162_rn(k0,k1);
  g_vtb[(b*64 + 2*l  )*256 + mm] = __float2bfloat16(vv0);
  g_vtb[(b*64 + 2*l+1)*256 + mm] = __float2bfloat16(vv1);
}

// =====================================================================
// kD: bf16 HMMA attention via mma.sync.m16n8k16.
// 256 thr = 8 warps x 16 q = 128 q/block. K [256][72] and V^T [64][264]
// bf16 in smem (padded, conflict-free); per-warp P [16][264] bf16.
// Softmax: no max-sub (scores ~N(0,0.03)), deferred normalization.
// =====================================================================
#define KD_LDK 72
#define KD_LDP 264
__global__ void __launch_bounds__(256) kD(){
  extern __shared__ __nv_bfloat16 smd[];
  __nv_bfloat16* Ks  = smd;                 // [256][72]   = 36864 B
  __nv_bfloat16* VTs = Ks + 256*KD_LDK;     // [64][264]   = 33792 B
  __nv_bfloat16* Ps  = VTs + 64*KD_LDP;     // 8 x [16][264] = 67584 B
  int t = threadIdx.x;
  int w = t>>5, l = t&31;
  int gid = l>>2, tid4 = l&3;
  int b  = blockIdx.x >> 7;
  int q0 = blockIdx.x * 128;

  // ---- stage K and V^T (uint4 = 8 bf16)
  {
    const uint4* kg = (const uint4*)(g_kb + (size_t)b*16384);
    for (int i=t;i<2048;i+=256){
      int row = i>>3, col = (i&7)*8;
      *(uint4*)(Ks + row*KD_LDK + col) = kg[i];
    }
    const uint4* vg = (const uint4*)(g_vtb + (size_t)b*16384);
    for (int i=t;i<2048;i+=256){
      int row = i>>5, col = (i&31)*8;
      *(uint4*)(VTs + row*KD_LDP + col) = vg[i];
    }
  }
  // ---- load Q A-fragments straight from global (row-major A)
  uint32_t qa[4][4];
  {
    int r1 = q0 + w*16 + gid, r2 = r1 + 8;
#pragma unroll
    for (int kc=0;kc<4;kc++){
      int c = kc*16 + tid4*2;
      qa[kc][0] = *(const uint32_t*)(g_qb + (size_t)r1*64 + c);
      qa[kc][1] = *(const uint32_t*)(g_qb + (size_t)r2*64 + c);
      qa[kc][2] = *(const uint32_t*)(g_qb + (size_t)r1*64 + c + 8);
      qa[kc][3] = *(const uint32_t*)(g_qb + (size_t)r2*64 + c + 8);
    }
  }
  __syncthreads();

  __nv_bfloat16* Pw = Ps + w*16*KD_LDP;
  float rs1 = 0.f, rs2 = 0.f;   // row sums for rows gid and gid+8

  // ---- QK + exp, 4 chunks of 64 keys
#pragma unroll
  for (int ch=0; ch<4; ch++){
    float acc[8][4];
#pragma unroll
    for (int nt=0;nt<8;nt++){ acc[nt][0]=0;acc[nt][1]=0;acc[nt][2]=0;acc[nt][3]=0; }
#pragma unroll
    for (int kc=0;kc<4;kc++){
#pragma unroll
      for (int nt=0;nt<8;nt++){
        int m = ch*64 + nt*8 + gid;
        uint32_t bfr[2];
        bfr[0] = *(const uint32_t*)(Ks + m*KD_LDK + kc*16 + tid4*2);
        bfr[1] = *(const uint32_t*)(Ks + m*KD_LDK + kc*16 + tid4*2 + 8);
        mma16816(acc[nt], qa[kc], bfr, acc[nt]);
      }
    }
#pragma unroll
    for (int nt=0;nt<8;nt++){
      float e0 = __expf(acc[nt][0]);
      float e1 = __expf(acc[nt][1]);
      float e2 = __expf(acc[nt][2]);
      float e3 = __expf(acc[nt][3]);
      rs1 += e0 + e1; rs2 += e2 + e3;
      int col = ch*64 + nt*8 + tid4*2;
      __nv_bfloat162 p01 = __floats2bfloat162_rn(e0,e1);
      __nv_bfloat162 p23 = __floats2bfloat162_rn(e2,e3);
      *(uint32_t*)(Pw + gid*KD_LDP + col)     = *(uint32_t*)&p01;
      *(uint32_t*)(Pw + (gid+8)*KD_LDP + col) = *(uint32_t*)&p23;
    }
  }
  // reduce row sums across the lane quartet
  rs1 += __shfl_xor_sync(0xffffffffu, rs1, 1);
  rs1 += __shfl_xor_sync(0xffffffffu, rs1, 2);
  rs2 += __shfl_xor_sync(0xffffffffu, rs2, 1);
  rs2 += __shfl_xor_sync(0xffffffffu, rs2, 2);
  __syncwarp();   // P is per-warp: warp-local visibility is enough

  // ---- AV: D[16][64] = P[16][256] @ V
  float o[8][4];
#pragma unroll
  for (int nt=0;nt<8;nt++){ o[nt][0]=0;o[nt][1]=0;o[nt][2]=0;o[nt][3]=0; }
#pragma unroll 4
  for (int kc=0;kc<16;kc++){
    uint32_t pa[4];
    int c = kc*16 + tid4*2;
    pa[0] = *(const uint32_t*)(Pw + gid*KD_LDP + c);
    pa[1] = *(const uint32_t*)(Pw + (gid+8)*KD_LDP + c);
    pa[2] = *(const uint32_t*)(Pw + gid*KD_LDP + c + 8);
    pa[3] = *(const uint32_t*)(Pw + (gid+8)*KD_LDP + c + 8);
#pragma unroll
    for (int nt=0;nt<8;nt++){
      int vc = nt*8 + gid;
      uint32_t bfr[2];
      bfr[0] = *(const uint32_t*)(VTs + vc*KD_LDP + c);
      bfr[1] = *(const uint32_t*)(VTs + vc*KD_LDP + c + 8);
      mma16816(o[nt], pa, bfr, o[nt]);
    }
  }
  // ---- scale by 1/rowsum and store
  float inv1 = __frcp_rn(rs1), inv2 = __frcp_rn(rs2);
  int r1 = q0 + w*16 + gid, r2 = r1 + 8;
#pragma unroll
  for (int nt=0;nt<8;nt++){
    int col = nt*8 + tid4*2;
    *(float2*)(g_o + (size_t)r1*64 + col) = make_float2(o[nt][0]*inv1, o[nt][1]*inv1);
    *(float2*)(g_o + (size_t)r2*64 + col) = make_float2(o[nt][2]*inv2, o[nt][3]*inv2);
  }
}

// =====================================================================
// kE: x_new = x + o@proj_w + proj_b (-> d_out), LN2, fc1 -> g_f.
// =====================================================================
__global__ void __launch_bounds__(256) kE(const float* __restrict__ x,
    const float* __restrict__ pw, const float* __restrict__ pb,
    const float* __restrict__ l2g, const float* __restrict__ l2b,
    const float* __restrict__ f1w, const float* __restrict__ f1b,
    float* __restrict__ out){
  extern __shared__ float sm[];
  float* pws  = sm;
  float* f1ws = pws + 4096;
  float* hs   = f1ws + 16384;
  int t = threadIdx.x;
  for (int i=t;i<4096;i+=256)  pws[i]=pw[i];
  for (int i=t;i<16384;i+=256) f1ws[i]=f1w[i];
  __syncthreads();
  int w=t>>5, l=t&31;
  float* hw = hs + w*512;
  const float2 pbv = *(const float2*)(pb + 2*l);
  const u64 pbp = pk2(pbv.x, pbv.y);
  const float lg0=l2g[2*l], lg1=l2g[2*l+1], lb0=l2b[2*l], lb1=l2b[2*l+1];
  u64 fbp[4];
#pragma unroll
  for (int j=0;j<4;j++){ int cc=2*(32*j+l); fbp[j]=pk2(f1b[cc], f1b[cc+1]); }
  for (int task=blockIdx.x; task<2048; task+=1024){
    int base = task*64 + w*8;
#pragma unroll
    for (int i=0;i<8;i++){
      float2 o2 = *(const float2*)(g_o + (base+i)*64 + 2*l);
      hw[i*64+2*l]=o2.x; hw[i*64+2*l+1]=o2.y;
    }
    __syncwarp();
    u64 acc[8];
#pragma unroll
    for (int i=0;i<8;i++) acc[i]=pbp;
#pragma unroll 8
    for (int k=0;k<64;k++){
      const float2 w2 = *(const float2*)(pws + k*64 + 2*l);
      u64 wp = pk2(w2.x,w2.y);
#pragma unroll
      for (int i=0;i<8;i++){
        float ob = hw[i*64+k];
        acc[i] = ffma2(pk2(ob,ob), wp, acc[i]);
      }
    }
    float h0v[8], h1v[8];
#pragma unroll
    for (int i=0;i<8;i++){
      float2 xv = *(const float2*)(x + (base+i)*64 + 2*l);
      float a0,a1; upk2(acc[i],a0,a1);
      float xn0 = xv.x + a0, xn1 = xv.y + a1;
      *(float2*)(out + (base+i)*64 + 2*l) = make_float2(xn0,xn1);
      float mn = wsum(xn0+xn1)*(1.f/64.f);
      float s2 = wsum(xn0*xn0+xn1*xn1)*(1.f/64.f);
      float rs = rsqrtf(fmaxf(s2-mn*mn,0.f)+1e-5f);
      h0v[i] = (xn0-mn)*rs*lg0+lb0;
      h1v[i] = (xn1-mn)*rs*lg1+lb1;
    }
    __syncwarp();
#pragma unroll
    for (int i=0;i<8;i++){ hw[i*64+2*l]=h0v[i]; hw[i*64+2*l+1]=h1v[i]; }
    __syncwarp();
    u64 f[8][4];
#pragma unroll
    for (int i=0;i<8;i++)
#pragma unroll
      for (int j=0;j<4;j++) f[i][j]=fbp[j];
#pragma unroll 4
    for (int k=0;k<64;k++){
      u64 wp[4];
#pragma unroll
      for (int j=0;j<4;j++){
        const float2 w2 = *(const float2*)(f1ws + k*256 + 2*(32*j+l));
        wp[j]=pk2(w2.x,w2.y);
      }
#pragma unroll
      for (int i=0;i<8;i++){
        float hb = hw[i*64+k];
        u64 hp = pk2(hb,hb);
#pragma unroll
        for (int j=0;j<4;j++) f[i][j]=ffma2(hp, wp[j], f[i][j]);
      }
    }
#pragma unroll
    for (int i=0;i<8;i++)
#pragma unroll
      for (int j=0;j<4;j++){
        float u,v; upk2(f[i][j],u,v);
        *(float2*)(g_f + (size_t)(base+i)*256 + 2*(32*j+l)) = make_float2(u,v);
      }
    __syncwarp();
  }
}

// =====================================================================
// kG: 3x3 depthwise (SAME) + exact GELU + fc2 + residual into d_out.
// =====================================================================
__global__ void __launch_bounds__(256) kG(const float* __restrict__ dww,
    const float* __restrict__ f2w, const float* __restrict__ f2b,
    float* __restrict__ out){
  extern __shared__ float sm[];
  float* f2ws = sm;
  float* fs   = f2ws + 16384;
  float* gsm  = fs + 6528;
  int t = threadIdx.x;
  for (int i=t;i<16384;i+=256) f2ws[i]=f2w[i];
  __syncthreads();
  int w=t>>5, l=t&31;
  const float2 bb = *(const float2*)(f2b + 2*l);
  for (int seg=blockIdx.x; seg<4096; seg+=1024){
    int b  = seg >> 9;
    int sb = seg & 511;
    int y  = sb >> 2;
    int x0 = (sb & 3)*32;
    u64 oacc[4] = {0,0,0,0};
    for (int cc=0; cc<4; cc++){
      int ch0 = cc*64;
      __syncthreads();
      for (int i2=t; i2<3264; i2+=256){
        int c  = (i2 & 31)*2;
        int pr = i2 >> 5;
        int px = pr % 34;
        int ry = pr / 34;
        int gy = y - 1 + ry;
        int gx = x0 - 1 + px;
        float2 v = make_float2(0.f,0.f);
        if ((unsigned)gy < 128u && (unsigned)gx < 128u)
          v = *(const float2*)(g_f + ((size_t)(b*16384) + gy*128 + gx)*256 + ch0 + c);
        *(float2*)(fs + (ry*34 + px)*64 + c) = v;
      }
      float2 dwr[9];
#pragma unroll
      for (int kk=0;kk<9;kk++) dwr[kk] = *(const float2*)(dww + kk*256 + ch0 + 2*l);
      __syncthreads();
#pragma unroll
      for (int p=0;p<4;p++){
        int P = w*4 + p;
        u64 ga = 0;
#pragma unroll
        for (int ky=0;ky<3;ky++)
#pragma unroll
          for (int kx=0;kx<3;kx++){
            float2 fv = *(const float2*)(fs + (ky*34 + P + kx)*64 + 2*l);
            ga = ffma2(pk2(fv.x,fv.y), pk2(dwr[ky*3+kx].x, dwr[ky*3+kx].y), ga);
          }
        float v0,v1; upk2(ga,v0,v1);
        v0 = 0.5f*v0*(1.f + erff(v0*0.70710678118f));
        v1 = 0.5f*v1*(1.f + erff(v1*0.70710678118f));
        *(float2*)(gsm + P*64 + 2*l) = make_float2(v0,v1);
      }
      __syncwarp();
#pragma unroll
      for (int p=0;p<4;p++){
        int P = w*4 + p;
#pragma unroll 8
        for (int k=0;k<64;k++){
          float gb = gsm[P*64 + k];
          const float2 w2 = *(const float2*)(f2ws + (ch0+k)*64 + 2*l);
          oacc[p] = ffma2(pk2(gb,gb), pk2(w2.x,w2.y), oacc[p]);
        }
      }
      __syncwarp();
    }
#pragma unroll
    for (int p=0;p<4;p++){
      int P = w*4 + p;
      int idx = ((b*16384) + y*128 + x0 + P)*64 + 2*l;
      float2 r = *(float2*)(out + idx);
      float a0,a1; upk2(oacc[p],a0,a1);
      *(float2*)(out + idx) = make_float2(r.x + a0 + bb.x, r.y + a1 + bb.y);
    }
  }
}

// =====================================================================
extern "C" void kernel_launch(void* const* d_in, const int* in_sizes, int n_in,
                              void* d_out, int out_size){
  const float* x    = (const float*)d_in[0];
  const float* ln1g = (const float*)d_in[3];
  const float* ln1b = (const float*)d_in[4];
  const float* qw   = (const float*)d_in[5];
  const float* qb   = (const float*)d_in[6];
  const float* kvw  = (const float*)d_in[7];
  const float* kvb  = (const float*)d_in[8];
  const float* pw   = (const float*)d_in[9];
  const float* pb   = (const float*)d_in[10];
  const float* srw  = (const float*)d_in[11];
  const float* srb  = (const float*)d_in[12];
  const float* sng  = (const float*)d_in[13];
  const float* snb  = (const float*)d_in[14];
  const float* l2g  = (const float*)d_in[15];
  const float* l2b  = (const float*)d_in[16];
  const float* f1w  = (const float*)d_in[17];
  const float* f1b  = (const float*)d_in[18];
  const float* dww  = (const float*)d_in[19];
  const float* f2w  = (const float*)d_in[20];
  const float* f2b  = (const float*)d_in[21];
  float* out = (float*)d_out;

  size_t smD = (size_t)(256*KD_LDK + 64*KD_LDP + 8*16*KD_LDP) * sizeof(__nv_bfloat16); // ~135 KB
  size_t smE = (size_t)(4096 + 16384 + 4096) * sizeof(float); // 96 KB
  size_t smG = (size_t)(16384 + 6528 + 2048) * sizeof(float); // ~98 KB
  cudaFuncSetAttribute(kD, cudaFuncAttributeMaxDynamicSharedMemorySize, (int)smD);
  cudaFuncSetAttribute(kE, cudaFuncAttributeMaxDynamicSharedMemorySize, (int)smE);
  cudaFuncSetAttribute(kG, cudaFuncAttributeMaxDynamicSharedMemorySize, (int)smG);

  kA<<<1024, 256>>>(x, ln1g, ln1b, qw, qb);
  kB<<<dim3(64,8), 256>>>(srw);
  kC<<<256, 256>>>(srb, sng, snb, kvw, kvb);
  kD<<<1024, 256, smD>>>();
  kE<<<1024, 256, smE>>>(x, pw, pb, l2g, l2b, f1w, f1b, out);
  kG<<<1024, 256, smG>>>(dww, f2w, f2b, out);
}

// round 15
// speedup vs baseline: 2.9776x; 2.9776x over previous
#include <cuda_runtime.h>
#include <cuda_bf16.h>
#include <math.h>
#include <stdint.h>

typedef unsigned long long u64;
#define DI __device__ __forceinline__

// ---------------- packed f32x2 helpers (FFMA2 only via PTX) ----------------
DI u64 pk2(float x, float y){ u64 r; asm("mov.b64 %0,{%1,%2};" : "=l"(r) : "f"(x), "f"(y)); return r; }
DI void upk2(u64 v, float& x, float& y){ asm("mov.b64 {%0,%1},%2;" : "=f"(x), "=f"(y) : "l"(v)); }
DI u64 ffma2(u64 a, u64 b, u64 c){ u64 d; asm("fma.rn.f32x2 %0,%1,%2,%3;" : "=l"(d) : "l"(a), "l"(b), "l"(c)); return d; }

DI float wsum(float v){
#pragma unroll
  for(int o=16;o;o>>=1) v += __shfl_xor_sync(0xffffffffu, v, o);
  return v;
}
DI float qsum(float v){  // sum over the 4-lane quartet (lanes sharing l>>2)
  v += __shfl_xor_sync(0xffffffffu, v, 1);
  v += __shfl_xor_sync(0xffffffffu, v, 2);
  return v;
}
DI uint32_t bf2(float a, float b){
  __nv_bfloat162 t = __floats2bfloat162_rn(a, b);
  return *(uint32_t*)&t;
}

// ---------------- warp-level bf16 HMMA (plain PTX, works on sm_103) --------
DI void mma16816(float* d, const uint32_t* a, const uint32_t* b, const float* c){
  asm volatile("mma.sync.aligned.m16n8k16.row.col.f32.bf16.bf16.f32 "
    "{%0,%1,%2,%3}, {%4,%5,%6,%7}, {%8,%9}, {%10,%11,%12,%13};"
    : "=f"(d[0]),"=f"(d[1]),"=f"(d[2]),"=f"(d[3])
    : "r"(a[0]),"r"(a[1]),"r"(a[2]),"r"(a[3]), "r"(b[0]),"r"(b[1]),
      "f"(c[0]),"f"(c[1]),"f"(c[2]),"f"(c[3]));
}

// Shapes: B=8, H=W=128, N=16384, C=64, heads=1, hd=64, R=8, Nr=256, HID=256

// ---------------- scratch ----------------
__device__ float g_h  [8*16384*64];
__device__ float g_o  [8*16384*64];
__device__ float g_xrp[8*2048*64];
__device__ __nv_bfloat16 g_fb [8*16384*256]; // fc1 output bf16
__device__ __nv_bfloat16 g_qb [8*16384*64];  // Q bf16 (pre-scaled 1/8)
__device__ __nv_bfloat16 g_kb [8*256*64];    // K bf16 [b][m][c]
__device__ __nv_bfloat16 g_vtb[8*64*256];    // V^T bf16 [b][c][m]

// =====================================================================
// kA: LN1 + q projection -> bf16 Q. Warp handles 8 rows.
// =====================================================================
__global__ void __launch_bounds__(256) kA(const float* __restrict__ x,
    const float* __restrict__ g1, const float* __restrict__ b1,
    const float* __restrict__ qw, const float* __restrict__ qb){
  __shared__ float qws[64*64];
  __shared__ float hs[8][8*64];
  __shared__ float gs[64], bs[64], qbs[64];
  int t = threadIdx.x;
  for (int i=t;i<4096;i+=256) qws[i]=qw[i];
  if (t<64){ gs[t]=g1[t]; bs[t]=b1[t]; qbs[t]=qb[t]; }
  __syncthreads();
  int w=t>>5, l=t&31;
  float* hw = hs[w];
  float g0=gs[2*l], g1v=gs[2*l+1], b0=bs[2*l], b1v=bs[2*l+1];
  u64 qbp = pk2(qbs[2*l], qbs[2*l+1]);
  for (int task=blockIdx.x; task<2048; task+=1024){
    int base = task*64 + w*8;
#pragma unroll
    for (int i=0;i<8;i++){
      const float2 xv = *(const float2*)(x + (base+i)*64 + 2*l);
      float m  = wsum(xv.x + xv.y) * (1.f/64.f);
      float s2 = wsum(xv.x*xv.x + xv.y*xv.y) * (1.f/64.f);
      float rs = rsqrtf(fmaxf(s2 - m*m, 0.f) + 1e-5f);
      float h0 = (xv.x - m)*rs*g0 + b0;
      float h1 = (xv.y - m)*rs*g1v + b1v;
      *(float2*)(g_h + (base+i)*64 + 2*l) = make_float2(h0, h1);
      hw[i*64 + 2*l] = h0; hw[i*64 + 2*l+1] = h1;
    }
    __syncwarp();
    u64 acc[8];
#pragma unroll
    for (int i=0;i<8;i++) acc[i]=qbp;
#pragma unroll 8
    for (int k=0;k<64;k++){
      const float2 wv = *(const float2*)(qws + k*64 + 2*l);
      u64 wp = pk2(wv.x, wv.y);
#pragma unroll
      for (int i=0;i<8;i++){
        float hv = hw[i*64 + k];
        acc[i] = ffma2(pk2(hv,hv), wp, acc[i]);
      }
    }
#pragma unroll
    for (int i=0;i<8;i++){
      float o0,o1; upk2(acc[i],o0,o1);
      *(uint32_t*)(g_qb + (base+i)*64 + 2*l) = bf2(o0*0.125f, o1*0.125f);
    }
    __syncwarp();
  }
}

// =====================================================================
// kB: SR conv as GEMM M=2048,K=4096,N=64. grid(64,8), K split by ky.
// =====================================================================
__global__ void __launch_bounds__(256) kB(const float* __restrict__ srw){
  __shared__ float As[32*64];
  __shared__ float Ws[64*64];
  int t = threadIdx.x;
  int m0 = blockIdx.x*32;
  int ky = blockIdx.y;
  int g = t>>5, l = t&31;
  int c2 = l*2;
  int b = m0 >> 8;
  u64 acc[4] = {0,0,0,0};
  for (int kx=0; kx<8; kx++){
    for (int i2=t; i2<1024; i2+=256){
      int r = i2>>5; int ci = (i2&31)*2;
      int mm = (m0 + r) & 255;
      int oy = mm>>4, ox = mm&15;
      const float2 v = *(const float2*)(g_h + ((b*16384) + (oy*8+ky)*128 + (ox*8+kx))*64 + ci);
      *(float2*)(As + r*64 + ci) = v;
    }
    const float* wsl = srw + ((ky*8+kx)*64)*64;
    for (int i2=t; i2<2048; i2+=256)
      *(float2*)(Ws + i2*2) = *(const float2*)(wsl + i2*2);
    __syncthreads();
#pragma unroll 8
    for (int ci=0; ci<64; ci++){
      const float2 w2 = *(const float2*)(Ws + ci*64 + c2);
      u64 wp = pk2(w2.x, w2.y);
#pragma unroll
      for (int j=0;j<4;j++){
        float a = As[(g + 8*j)*64 + ci];
        acc[j] = ffma2(pk2(a,a), wp, acc[j]);
      }
    }
    __syncthreads();
  }
#pragma unroll
  for (int j=0;j<4;j++){
    float o0,o1; upk2(acc[j],o0,o1);
    *(float2*)(g_xrp + ((ky*2048) + m0 + g + 8*j)*64 + c2) = make_float2(o0,o1);
  }
}

// =====================================================================
// kC: sum conv partials + sr_b + LN + kv projection -> bf16 K, V^T.
// =====================================================================
__global__ void __launch_bounds__(256) kC(const float* __restrict__ srb,
    const float* __restrict__ sg, const float* __restrict__ sb,
    const float* __restrict__ kvw, const float* __restrict__ kvb){
  __shared__ float kws[64*128];
  __shared__ float hs[8][64];
  int t = threadIdx.x;
  for (int i=t;i<8192;i+=256) kws[i]=kvw[i];
  __syncthreads();
  int w=t>>5, l=t&31;
  int m = blockIdx.x*8 + w;
  float v0 = srb[2*l], v1 = srb[2*l+1];
#pragma unroll
  for (int p=0;p<8;p++){
    const float2 a = *(const float2*)(g_xrp + (p*2048+m)*64 + 2*l);
    v0 += a.x; v1 += a.y;
  }
  float mn = wsum(v0+v1)*(1.f/64.f);
  float s2 = wsum(v0*v0+v1*v1)*(1.f/64.f);
  float rs = rsqrtf(fmaxf(s2-mn*mn,0.f)+1e-5f);
  float h0 = (v0-mn)*rs*sg[2*l]+sb[2*l];
  float h1 = (v1-mn)*rs*sg[2*l+1]+sb[2*l+1];
  hs[w][2*l]=h0; hs[w][2*l+1]=h1;
  __syncwarp();
  u64 ak = pk2(kvb[2*l], kvb[2*l+1]);
  u64 av = pk2(kvb[64+2*l], kvb[64+2*l+1]);
#pragma unroll 8
  for (int k=0;k<64;k++){
    float hb = hs[w][k];
    u64 hp = pk2(hb,hb);
    const float2 wk = *(const float2*)(kws + k*128 + 2*l);
    const float2 wv = *(const float2*)(kws + k*128 + 64 + 2*l);
    ak = ffma2(hp, pk2(wk.x,wk.y), ak);
    av = ffma2(hp, pk2(wv.x,wv.y), av);
  }
  int b = m>>8, mm = m&255;
  float k0,k1,vv0,vv1; upk2(ak,k0,k1); upk2(av,vv0,vv1);
  *(uint32_t*)(g_kb + (b*256+mm)*64 + 2*l) = bf2(k0,k1);
  g_vtb[(b*64 + 2*l  )*256 + mm] = __float2bfloat16(vv0);
  g_vtb[(b*64 + 2*l+1)*256 + mm] = __float2bfloat16(vv1);
}

// =====================================================================
// kD: bf16 HMMA attention (unchanged from passing R13 version).
// =====================================================================
#define KD_LDK 72
#define KD_LDP 264
__global__ void __launch_bounds__(256) kD(){
  extern __shared__ __nv_bfloat16 smd[];
  __nv_bfloat16* Ks  = smd;
  __nv_bfloat16* VTs = Ks + 256*KD_LDK;
  __nv_bfloat16* Ps  = VTs + 64*KD_LDP;
  int t = threadIdx.x;
  int w = t>>5, l = t&31;
  int gid = l>>2, tid4 = l&3;
  int b  = blockIdx.x >> 7;
  int q0 = blockIdx.x * 128;
  {
    const uint4* kg = (const uint4*)(g_kb + (size_t)b*16384);
    for (int i=t;i<2048;i+=256){
      int row = i>>3, col = (i&7)*8;
      *(uint4*)(Ks + row*KD_LDK + col) = kg[i];
    }
    const uint4* vg = (const uint4*)(g_vtb + (size_t)b*16384);
    for (int i=t;i<2048;i+=256){
      int row = i>>5, col = (i&31)*8;
      *(uint4*)(VTs + row*KD_LDP + col) = vg[i];
    }
  }
  uint32_t qa[4][4];
  {
    int r1 = q0 + w*16 + gid, r2 = r1 + 8;
#pragma unroll
    for (int kc=0;kc<4;kc++){
      int c = kc*16 + tid4*2;
      qa[kc][0] = *(const uint32_t*)(g_qb + (size_t)r1*64 + c);
      qa[kc][1] = *(const uint32_t*)(g_qb + (size_t)r2*64 + c);
      qa[kc][2] = *(const uint32_t*)(g_qb + (size_t)r1*64 + c + 8);
      qa[kc][3] = *(const uint32_t*)(g_qb + (size_t)r2*64 + c + 8);
    }
  }
  __syncthreads();
  __nv_bfloat16* Pw = Ps + w*16*KD_LDP;
  float rs1 = 0.f, rs2 = 0.f;
#pragma unroll
  for (int ch=0; ch<4; ch++){
    float acc[8][4];
#pragma unroll
    for (int nt=0;nt<8;nt++){ acc[nt][0]=0;acc[nt][1]=0;acc[nt][2]=0;acc[nt][3]=0; }
#pragma unroll
    for (int kc=0;kc<4;kc++){
#pragma unroll
      for (int nt=0;nt<8;nt++){
        int m = ch*64 + nt*8 + gid;
        uint32_t bfr[2];
        bfr[0] = *(const uint32_t*)(Ks + m*KD_LDK + kc*16 + tid4*2);
        bfr[1] = *(const uint32_t*)(Ks + m*KD_LDK + kc*16 + tid4*2 + 8);
        mma16816(acc[nt], qa[kc], bfr, acc[nt]);
      }
    }
#pragma unroll
    for (int nt=0;nt<8;nt++){
      float e0 = __expf(acc[nt][0]);
      float e1 = __expf(acc[nt][1]);
      float e2 = __expf(acc[nt][2]);
      float e3 = __expf(acc[nt][3]);
      rs1 += e0 + e1; rs2 += e2 + e3;
      int col = ch*64 + nt*8 + tid4*2;
      *(uint32_t*)(Pw + gid*KD_LDP + col)     = bf2(e0,e1);
      *(uint32_t*)(Pw + (gid+8)*KD_LDP + col) = bf2(e2,e3);
    }
  }
  rs1 = qsum(rs1); rs2 = qsum(rs2);
  __syncwarp();
  float o[8][4];
#pragma unroll
  for (int nt=0;nt<8;nt++){ o[nt][0]=0;o[nt][1]=0;o[nt][2]=0;o[nt][3]=0; }
#pragma unroll 4
  for (int kc=0;kc<16;kc++){
    uint32_t pa[4];
    int c = kc*16 + tid4*2;
    pa[0] = *(const uint32_t*)(Pw + gid*KD_LDP + c);
    pa[1] = *(const uint32_t*)(Pw + (gid+8)*KD_LDP + c);
    pa[2] = *(const uint32_t*)(Pw + gid*KD_LDP + c + 8);
    pa[3] = *(const uint32_t*)(Pw + (gid+8)*KD_LDP + c + 8);
#pragma unroll
    for (int nt=0;nt<8;nt++){
      int vc = nt*8 + gid;
      uint32_t bfr[2];
      bfr[0] = *(const uint32_t*)(VTs + vc*KD_LDP + c);
      bfr[1] = *(const uint32_t*)(VTs + vc*KD_LDP + c + 8);
      mma16816(o[nt], pa, bfr, o[nt]);
    }
  }
  float inv1 = __frcp_rn(rs1), inv2 = __frcp_rn(rs2);
  int r1 = q0 + w*16 + gid, r2 = r1 + 8;
#pragma unroll
  for (int nt=0;nt<8;nt++){
    int col = nt*8 + tid4*2;
    *(float2*)(g_o + (size_t)r1*64 + col) = make_float2(o[nt][0]*inv1, o[nt][1]*inv1);
    *(float2*)(g_o + (size_t)r2*64 + col) = make_float2(o[nt][2]*inv2, o[nt][3]*inv2);
  }
}

// =====================================================================
// kE (HMMA): x_new = x + o@proj_w + pb (-> out), LN2, fc1 -> g_fb (bf16).
// grid 1024, block 256 = 8 warps x 16 rows = 128 rows/block.
// =====================================================================
__global__ void __launch_bounds__(256) kE(const float* __restrict__ x,
    const float* __restrict__ pw, const float* __restrict__ pb,
    const float* __restrict__ l2g, const float* __restrict__ l2b,
    const float* __restrict__ f1w, const float* __restrict__ f1b,
    float* __restrict__ out){
  extern __shared__ __nv_bfloat16 smE_[];
  __nv_bfloat16* pwT = smE_;            // [64][72]   proj_w^T
  __nv_bfloat16* Wt  = pwT + 64*72;     // [256][72]  fc1_w^T
  __nv_bfloat16* h2s = Wt + 256*72;     // 8 x [16][72]
  int t=threadIdx.x, w=t>>5, l=t&31, gid=l>>2, tid4=l&3;
  for (int i=t;i<4096;i+=256){ int k=i>>6, n=i&63; pwT[n*72+k] = __float2bfloat16(pw[i]); }
  for (int i=t;i<16384;i+=256){ int k=i>>8, n=i&255; Wt[n*72+k] = __float2bfloat16(f1w[i]); }
  __syncthreads();
  int r1 = blockIdx.x*128 + w*16 + gid;
  int r2 = r1 + 8;
  // ---- o A-fragments (bf16 from f32 global)
  uint32_t oa[4][4];
#pragma unroll
  for (int kc=0;kc<4;kc++){
    int c = kc*16 + tid4*2;
    float2 v;
    v = *(const float2*)(g_o + (size_t)r1*64 + c);   oa[kc][0]=bf2(v.x,v.y);
    v = *(const float2*)(g_o + (size_t)r2*64 + c);   oa[kc][1]=bf2(v.x,v.y);
    v = *(const float2*)(g_o + (size_t)r1*64 + c+8); oa[kc][2]=bf2(v.x,v.y);
    v = *(const float2*)(g_o + (size_t)r2*64 + c+8); oa[kc][3]=bf2(v.x,v.y);
  }
  // ---- proj mma
  float pr[8][4];
#pragma unroll
  for (int nt=0;nt<8;nt++){ pr[nt][0]=0;pr[nt][1]=0;pr[nt][2]=0;pr[nt][3]=0; }
#pragma unroll
  for (int kc=0;kc<4;kc++)
#pragma unroll
    for (int nt=0;nt<8;nt++){
      uint32_t bfr[2];
      bfr[0] = *(const uint32_t*)(pwT + (nt*8+gid)*72 + kc*16 + tid4*2);
      bfr[1] = *(const uint32_t*)(pwT + (nt*8+gid)*72 + kc*16 + tid4*2 + 8);
      mma16816(pr[nt], oa[kc], bfr, pr[nt]);
    }
  // ---- x + proj + pb -> out, LN partial sums
  float xn[8][4];
  float s1=0,q1=0,s2=0,q2=0;
#pragma unroll
  for (int nt=0;nt<8;nt++){
    int c0 = nt*8 + tid4*2;
    float2 bias = *(const float2*)(pb + c0);
    float2 x1 = *(const float2*)(x + (size_t)r1*64 + c0);
    float2 x2 = *(const float2*)(x + (size_t)r2*64 + c0);
    xn[nt][0] = x1.x + pr[nt][0] + bias.x;
    xn[nt][1] = x1.y + pr[nt][1] + bias.y;
    xn[nt][2] = x2.x + pr[nt][2] + bias.x;
    xn[nt][3] = x2.y + pr[nt][3] + bias.y;
    *(float2*)(out + (size_t)r1*64 + c0) = make_float2(xn[nt][0], xn[nt][1]);
    *(float2*)(out + (size_t)r2*64 + c0) = make_float2(xn[nt][2], xn[nt][3]);
    s1 += xn[nt][0]+xn[nt][1]; q1 += xn[nt][0]*xn[nt][0]+xn[nt][1]*xn[nt][1];
    s2 += xn[nt][2]+xn[nt][3]; q2 += xn[nt][2]*xn[nt][2]+xn[nt][3]*xn[nt][3];
  }
  s1=qsum(s1); q1=qsum(q1); s2=qsum(s2); q2=qsum(q2);
  float mn1=s1*(1.f/64.f), mn2=s2*(1.f/64.f);
  float iv1=rsqrtf(fmaxf(q1*(1.f/64.f)-mn1*mn1,0.f)+1e-5f);
  float iv2=rsqrtf(fmaxf(q2*(1.f/64.f)-mn2*mn2,0.f)+1e-5f);
  // ---- h2 -> per-warp smem tile bf16
  __nv_bfloat16* h2w = h2s + w*16*72;
#pragma unroll
  for (int nt=0;nt<8;nt++){
    int c0 = nt*8 + tid4*2;
    float2 gg = *(const float2*)(l2g + c0);
    float2 bb = *(const float2*)(l2b + c0);
    *(uint32_t*)(h2w + gid*72 + c0)     = bf2((xn[nt][0]-mn1)*iv1*gg.x+bb.x, (xn[nt][1]-mn1)*iv1*gg.y+bb.y);
    *(uint32_t*)(h2w + (gid+8)*72 + c0) = bf2((xn[nt][2]-mn2)*iv2*gg.x+bb.x, (xn[nt][3]-mn2)*iv2*gg.y+bb.y);
  }
  __syncwarp();
  // ---- fc1: A-frags from h2s, two halves of N=128
  uint32_t ha[4][4];
#pragma unroll
  for (int kc=0;kc<4;kc++){
    int c = kc*16 + tid4*2;
    ha[kc][0] = *(const uint32_t*)(h2w + gid*72 + c);
    ha[kc][1] = *(const uint32_t*)(h2w + (gid+8)*72 + c);
    ha[kc][2] = *(const uint32_t*)(h2w + gid*72 + c + 8);
    ha[kc][3] = *(const uint32_t*)(h2w + (gid+8)*72 + c + 8);
  }
#pragma unroll
  for (int nh=0;nh<2;nh++){
    float acc[16][4];
#pragma unroll
    for (int nt=0;nt<16;nt++){ acc[nt][0]=0;acc[nt][1]=0;acc[nt][2]=0;acc[nt][3]=0; }
#pragma unroll
    for (int kc=0;kc<4;kc++)
#pragma unroll
      for (int nt=0;nt<16;nt++){
        int n = nh*128 + nt*8 + gid;
        uint32_t bfr[2];
        bfr[0] = *(const uint32_t*)(Wt + n*72 + kc*16 + tid4*2);
        bfr[1] = *(const uint32_t*)(Wt + n*72 + kc*16 + tid4*2 + 8);
        mma16816(acc[nt], ha[kc], bfr, acc[nt]);
      }
#pragma unroll
    for (int nt=0;nt<16;nt++){
      int c0 = nh*128 + nt*8 + tid4*2;
      float2 fb = *(const float2*)(f1b + c0);
      *(uint32_t*)(g_fb + (size_t)r1*256 + c0) = bf2(acc[nt][0]+fb.x, acc[nt][1]+fb.y);
      *(uint32_t*)(g_fb + (size_t)r2*256 + c0) = bf2(acc[nt][2]+fb.x, acc[nt][3]+fb.y);
    }
  }
}

// =====================================================================
// kG (HMMA fc2): 3x3 depthwise (SAME, fp32) + exact GELU + fc2 + residual.
// grid 1024 = (b, y): one image row (128 px) per block.
// =====================================================================
__global__ void __launch_bounds__(256) kG(const float* __restrict__ dww,
    const float* __restrict__ f2w, const float* __restrict__ f2b,
    float* __restrict__ out){
  extern __shared__ __nv_bfloat16 smG_[];
  __nv_bfloat16* W2T = smG_;             // [64][264]  fc2_w^T
  __nv_bfloat16* fs  = W2T + 64*264;     // [390][72]  (3 rows x 130 px halo)
  __nv_bfloat16* gsm = fs + 390*72;      // [128][72]  gelu output
  int t=threadIdx.x, w=t>>5, l=t&31, gid=l>>2, tid4=l&3;
  for (int i=t;i<16384;i+=256){ int k=i>>6, n=i&63; W2T[n*264+k] = __float2bfloat16(f2w[i]); }
  int b = blockIdx.x>>7, y = blockIdx.x&127;
  int chp = t&31;      // channel pair (2 ch) within 64-chunk
  int pxb = t>>5;      // px base for dwconv (px = pxb + 8i)
  float acc[8][4];
#pragma unroll
  for (int nt=0;nt<8;nt++){ acc[nt][0]=0;acc[nt][1]=0;acc[nt][2]=0;acc[nt][3]=0; }
  for (int cc=0;cc<4;cc++){
    int ch0 = cc*64;
    // stage halo tile (bf16)
    for (int i=t;i<3120;i+=256){
      int r = i>>3, part = i&7;
      int ry = r/130, px = r%130;
      int gy = y-1+ry, gx = px-1;
      uint4 v = make_uint4(0,0,0,0);
      if ((unsigned)gy<128u && (unsigned)gx<128u)
        v = *(const uint4*)(g_fb + ((size_t)((b<<14) + gy*128 + gx))*256 + ch0 + part*8);
      *(uint4*)(fs + r*72 + part*8) = v;
    }
    float2 dwr[9];
#pragma unroll
    for (int kk=0;kk<9;kk++) dwr[kk] = *(const float2*)(dww + kk*256 + ch0 + chp*2);
    __syncthreads();  // fs ready; previous gsm fully consumed by mma
    // dwconv + gelu -> gsm
#pragma unroll
    for (int i=0;i<16;i++){
      int px = pxb + 8*i;
      u64 ga = 0;
#pragma unroll
      for (int ry=0;ry<3;ry++)
#pragma unroll
        for (int kx=0;kx<3;kx++){
          __nv_bfloat162 fv2 = *(const __nv_bfloat162*)(fs + (ry*130 + px + kx)*72 + chp*2);
          float2 fv = __bfloat1622float2(fv2);
          ga = ffma2(pk2(fv.x,fv.y), pk2(dwr[ry*3+kx].x, dwr[ry*3+kx].y), ga);
        }
      float v0,v1; upk2(ga,v0,v1);
      v0 = 0.5f*v0*(1.f + erff(v0*0.70710678118f));
      v1 = 0.5f*v1*(1.f + erff(v1*0.70710678118f));
      *(uint32_t*)(gsm + px*72 + chp*2) = bf2(v0,v1);
    }
    __syncthreads();  // gsm ready for all warps
    // fc2 chunk mma: D[16 px][64] += g[16][64] @ W2[ch0..ch0+63][64]
#pragma unroll
    for (int kc=0;kc<4;kc++){
      uint32_t pa[4];
      int c = kc*16 + tid4*2;
      pa[0] = *(const uint32_t*)(gsm + (w*16+gid)*72 + c);
      pa[1] = *(const uint32_t*)(gsm + (w*16+gid+8)*72 + c);
      pa[2] = *(const uint32_t*)(gsm + (w*16+gid)*72 + c + 8);
      pa[3] = *(const uint32_t*)(gsm + (w*16+gid+8)*72 + c + 8);
#pragma unroll
      for (int nt=0;nt<8;nt++){
        uint32_t bfr[2];
        bfr[0] = *(const uint32_t*)(W2T + (nt*8+gid)*264 + ch0 + c);
        bfr[1] = *(const uint32_t*)(W2T + (nt*8+gid)*264 + ch0 + c + 8);
        mma16816(acc[nt], pa, bfr, acc[nt]);
      }
    }
  }
  // residual RMW
  int p1 = w*16 + gid, p2 = p1 + 8;
  size_t base = ((size_t)(b<<14) + y*128);
#pragma unroll
  for (int nt=0;nt<8;nt++){
    int c0 = nt*8 + tid4*2;
    float2 bb = *(const float2*)(f2b + c0);
    float2 ra = *(float2*)(out + (base+p1)*64 + c0);
    float2 rb = *(float2*)(out + (base+p2)*64 + c0);
    *(float2*)(out + (base+p1)*64 + c0) = make_float2(ra.x + acc[nt][0] + bb.x, ra.y + acc[nt][1] + bb.y);
    *(float2*)(out + (base+p2)*64 + c0) = make_float2(rb.x + acc[nt][2] + bb.x, rb.y + acc[nt][3] + bb.y);
  }
}

// =====================================================================
extern "C" void kernel_launch(void* const* d_in, const int* in_sizes, int n_in,
                              void* d_out, int out_size){
  const float* x    = (const float*)d_in[0];
  const float* ln1g = (const float*)d_in[3];
  const float* ln1b = (const float*)d_in[4];
  const float* qw   = (const float*)d_in[5];
  const float* qb   = (const float*)d_in[6];
  const float* kvw  = (const float*)d_in[7];
  const float* kvb  = (const float*)d_in[8];
  const float* pw   = (const float*)d_in[9];
  const float* pb   = (const float*)d_in[10];
  const float* srw  = (const float*)d_in[11];
  const float* srb  = (const float*)d_in[12];
  const float* sng  = (const float*)d_in[13];
  const float* snb  = (const float*)d_in[14];
  const float* l2g  = (const float*)d_in[15];
  const float* l2b  = (const float*)d_in[16];
  const float* f1w  = (const float*)d_in[17];
  const float* f1b  = (const float*)d_in[18];
  const float* dww  = (const float*)d_in[19];
  const float* f2w  = (const float*)d_in[20];
  const float* f2b  = (const float*)d_in[21];
  float* out = (float*)d_out;

  size_t smD = (size_t)(256*KD_LDK + 64*KD_LDP + 8*16*KD_LDP) * sizeof(__nv_bfloat16); // ~135 KB
  size_t smE = (size_t)(64*72 + 256*72 + 8*16*72) * sizeof(__nv_bfloat16);             // ~63 KB
  size_t smG = (size_t)(64*264 + 390*72 + 128*72) * sizeof(__nv_bfloat16);             // ~106 KB
  cudaFuncSetAttribute(kD, cudaFuncAttributeMaxDynamicSharedMemorySize, (int)smD);
  cudaFuncSetAttribute(kE, cudaFuncAttributeMaxDynamicSharedMemorySize, (int)smE);
  cudaFuncSetAttribute(kG, cudaFuncAttributeMaxDynamicSharedMemorySize, (int)smG);

  kA<<<1024, 256>>>(x, ln1g, ln1b, qw, qb);
  kB<<<dim3(64,8), 256>>>(srw);
  kC<<<256, 256>>>(srb, sng, snb, kvw, kvb);
  kD<<<1024, 256, smD>>>();
  kE<<<1024, 256, smE>>>(x, pw, pb, l2g, l2b, f1w, f1b, out);
  kG<<<1024, 256, smG>>>(dww, f2w, f2b, out);
}

// round 16
// speedup vs baseline: 3.0567x; 1.0266x over previous
#include <cuda_runtime.h>
#include <cuda_bf16.h>
#include <math.h>
#include <stdint.h>

typedef unsigned long long u64;
#define DI __device__ __forceinline__

// ---------------- packed f32x2 helpers (FFMA2 only via PTX) ----------------
DI u64 pk2(float x, float y){ u64 r; asm("mov.b64 %0,{%1,%2};" : "=l"(r) : "f"(x), "f"(y)); return r; }
DI void upk2(u64 v, float& x, float& y){ asm("mov.b64 {%0,%1},%2;" : "=f"(x), "=f"(y) : "l"(v)); }
DI u64 ffma2(u64 a, u64 b, u64 c){ u64 d; asm("fma.rn.f32x2 %0,%1,%2,%3;" : "=l"(d) : "l"(a), "l"(b), "l"(c)); return d; }

DI float wsum(float v){
#pragma unroll
  for(int o=16;o;o>>=1) v += __shfl_xor_sync(0xffffffffu, v, o);
  return v;
}
DI float qsum(float v){  // sum over the 4-lane quartet
  v += __shfl_xor_sync(0xffffffffu, v, 1);
  v += __shfl_xor_sync(0xffffffffu, v, 2);
  return v;
}
DI uint32_t bf2(float a, float b){
  __nv_bfloat162 t = __floats2bfloat162_rn(a, b);
  return *(uint32_t*)&t;
}

// ---------------- warp-level bf16 HMMA (plain PTX, works on sm_103) --------
DI void mma16816(float* d, const uint32_t* a, const uint32_t* b, const float* c){
  asm volatile("mma.sync.aligned.m16n8k16.row.col.f32.bf16.bf16.f32 "
    "{%0,%1,%2,%3}, {%4,%5,%6,%7}, {%8,%9}, {%10,%11,%12,%13};"
    : "=f"(d[0]),"=f"(d[1]),"=f"(d[2]),"=f"(d[3])
    : "r"(a[0]),"r"(a[1]),"r"(a[2]),"r"(a[3]), "r"(b[0]),"r"(b[1]),
      "f"(c[0]),"f"(c[1]),"f"(c[2]),"f"(c[3]));
}

// Shapes: B=8, H=W=128, N=16384, C=64, heads=1, hd=64, R=8, Nr=256, HID=256

// ---------------- scratch ----------------
__device__ __nv_bfloat16 g_hb [8*16384*64]; // LN1 output bf16
__device__ float g_o  [8*16384*64];
__device__ float g_xrp[8*2048*64];
__device__ __nv_bfloat16 g_fb [8*16384*256]; // fc1 output bf16
__device__ __nv_bfloat16 g_qb [8*16384*64];  // Q bf16 (pre-scaled 1/8)
__device__ __nv_bfloat16 g_kb [8*256*64];    // K bf16 [b][m][c]
__device__ __nv_bfloat16 g_vtb[8*64*256];    // V^T bf16 [b][c][m]

// =====================================================================
// kA: LN1 + q projection -> bf16 Q, bf16 h. Warp handles 8 rows.
// =====================================================================
__global__ void __launch_bounds__(256) kA(const float* __restrict__ x,
    const float* __restrict__ g1, const float* __restrict__ b1,
    const float* __restrict__ qw, const float* __restrict__ qb){
  __shared__ float qws[64*64];
  __shared__ float hs[8][8*64];
  __shared__ float gs[64], bs[64], qbs[64];
  int t = threadIdx.x;
  for (int i=t;i<4096;i+=256) qws[i]=qw[i];
  if (t<64){ gs[t]=g1[t]; bs[t]=b1[t]; qbs[t]=qb[t]; }
  __syncthreads();
  int w=t>>5, l=t&31;
  float* hw = hs[w];
  float g0=gs[2*l], g1v=gs[2*l+1], b0=bs[2*l], b1v=bs[2*l+1];
  u64 qbp = pk2(qbs[2*l], qbs[2*l+1]);
  for (int task=blockIdx.x; task<2048; task+=1024){
    int base = task*64 + w*8;
#pragma unroll
    for (int i=0;i<8;i++){
      const float2 xv = *(const float2*)(x + (base+i)*64 + 2*l);
      float m  = wsum(xv.x + xv.y) * (1.f/64.f);
      float s2 = wsum(xv.x*xv.x + xv.y*xv.y) * (1.f/64.f);
      float rs = rsqrtf(fmaxf(s2 - m*m, 0.f) + 1e-5f);
      float h0 = (xv.x - m)*rs*g0 + b0;
      float h1 = (xv.y - m)*rs*g1v + b1v;
      *(uint32_t*)(g_hb + (size_t)(base+i)*64 + 2*l) = bf2(h0, h1);
      hw[i*64 + 2*l] = h0; hw[i*64 + 2*l+1] = h1;
    }
    __syncwarp();
    u64 acc[8];
#pragma unroll
    for (int i=0;i<8;i++) acc[i]=qbp;
#pragma unroll 8
    for (int k=0;k<64;k++){
      const float2 wv = *(const float2*)(qws + k*64 + 2*l);
      u64 wp = pk2(wv.x, wv.y);
#pragma unroll
      for (int i=0;i<8;i++){
        float hv = hw[i*64 + k];
        acc[i] = ffma2(pk2(hv,hv), wp, acc[i]);
      }
    }
#pragma unroll
    for (int i=0;i<8;i++){
      float o0,o1; upk2(acc[i],o0,o1);
      *(uint32_t*)(g_qb + (base+i)*64 + 2*l) = bf2(o0*0.125f, o1*0.125f);
    }
    __syncwarp();
  }
}

// =====================================================================
// kB: SR conv as GEMM M=2048,K=4096,N=64. grid(64,8), K split by ky.
// =====================================================================
__global__ void __launch_bounds__(256) kB(const float* __restrict__ srw){
  __shared__ float As[32*64];
  __shared__ float Ws[64*64];
  int t = threadIdx.x;
  int m0 = blockIdx.x*32;
  int ky = blockIdx.y;
  int g = t>>5, l = t&31;
  int c2 = l*2;
  int b = m0 >> 8;
  u64 acc[4] = {0,0,0,0};
  for (int kx=0; kx<8; kx++){
    for (int i2=t; i2<1024; i2+=256){
      int r = i2>>5; int ci = (i2&31)*2;
      int mm = (m0 + r) & 255;
      int oy = mm>>4, ox = mm&15;
      __nv_bfloat162 hv = *(const __nv_bfloat162*)(g_hb + (size_t)((b*16384) + (oy*8+ky)*128 + (ox*8+kx))*64 + ci);
      *(float2*)(As + r*64 + ci) = __bfloat1622float2(hv);
    }
    const float* wsl = srw + ((ky*8+kx)*64)*64;
    for (int i2=t; i2<2048; i2+=256)
      *(float2*)(Ws + i2*2) = *(const float2*)(wsl + i2*2);
    __syncthreads();
#pragma unroll 8
    for (int ci=0; ci<64; ci++){
      const float2 w2 = *(const float2*)(Ws + ci*64 + c2);
      u64 wp = pk2(w2.x, w2.y);
#pragma unroll
      for (int j=0;j<4;j++){
        float a = As[(g + 8*j)*64 + ci];
        acc[j] = ffma2(pk2(a,a), wp, acc[j]);
      }
    }
    __syncthreads();
  }
#pragma unroll
  for (int j=0;j<4;j++){
    float o0,o1; upk2(acc[j],o0,o1);
    *(float2*)(g_xrp + ((ky*2048) + m0 + g + 8*j)*64 + c2) = make_float2(o0,o1);
  }
}

// =====================================================================
// kC: sum conv partials + sr_b + LN + kv projection -> bf16 K, V^T.
// =====================================================================
__global__ void __launch_bounds__(256) kC(const float* __restrict__ srb,
    const float* __restrict__ sg, const float* __restrict__ sb,
    const float* __restrict__ kvw, const float* __restrict__ kvb){
  __shared__ float kws[64*128];
  __shared__ float hs[8][64];
  int t = threadIdx.x;
  for (int i=t;i<8192;i+=256) kws[i]=kvw[i];
  __syncthreads();
  int w=t>>5, l=t&31;
  int m = blockIdx.x*8 + w;
  float v0 = srb[2*l], v1 = srb[2*l+1];
#pragma unroll
  for (int p=0;p<8;p++){
    const float2 a = *(const float2*)(g_xrp + (p*2048+m)*64 + 2*l);
    v0 += a.x; v1 += a.y;
  }
  float mn = wsum(v0+v1)*(1.f/64.f);
  float s2 = wsum(v0*v0+v1*v1)*(1.f/64.f);
  float rs = rsqrtf(fmaxf(s2-mn*mn,0.f)+1e-5f);
  float h0 = (v0-mn)*rs*sg[2*l]+sb[2*l];
  float h1 = (v1-mn)*rs*sg[2*l+1]+sb[2*l+1];
  hs[w][2*l]=h0; hs[w][2*l+1]=h1;
  __syncwarp();
  u64 ak = pk2(kvb[2*l], kvb[2*l+1]);
  u64 av = pk2(kvb[64+2*l], kvb[64+2*l+1]);
#pragma unroll 8
  for (int k=0;k<64;k++){
    float hb = hs[w][k];
    u64 hp = pk2(hb,hb);
    const float2 wk = *(const float2*)(kws + k*128 + 2*l);
    const float2 wv = *(const float2*)(kws + k*128 + 64 + 2*l);
    ak = ffma2(hp, pk2(wk.x,wk.y), ak);
    av = ffma2(hp, pk2(wv.x,wv.y), av);
  }
  int b = m>>8, mm = m&255;
  float k0,k1,vv0,vv1; upk2(ak,k0,k1); upk2(av,vv0,vv1);
  *(uint32_t*)(g_kb + (b*256+mm)*64 + 2*l) = bf2(k0,k1);
  g_vtb[(b*64 + 2*l  )*256 + mm] = __float2bfloat16(vv0);
  g_vtb[(b*64 + 2*l+1)*256 + mm] = __float2bfloat16(vv1);
}

// =====================================================================
// kD: bf16 HMMA attention, REGISTER-RESIDENT P.
// The QK accumulator fragment layout == the AV A-fragment layout, so
// exp(acc) packs straight into bf16 regs (pbr[32][2]); no P smem at all.
// smem = K [256][72] + V^T [64][264] = 69 KB -> 2 blocks/SM.
// =====================================================================
#define KD_LDK 72
#define KD_LDP 264
__global__ void __launch_bounds__(256,2) kD(){
  extern __shared__ __nv_bfloat16 smd[];
  __nv_bfloat16* Ks  = smd;               // [256][72]
  __nv_bfloat16* VTs = Ks + 256*KD_LDK;   // [64][264]
  int t = threadIdx.x;
  int w = t>>5, l = t&31;
  int gid = l>>2, tid4 = l&3;
  int b  = blockIdx.x >> 7;
  int q0 = blockIdx.x * 128;
  {
    const uint4* kg = (const uint4*)(g_kb + (size_t)b*16384);
    for (int i=t;i<2048;i+=256){
      int row = i>>3, col = (i&7)*8;
      *(uint4*)(Ks + row*KD_LDK + col) = kg[i];
    }
    const uint4* vg = (const uint4*)(g_vtb + (size_t)b*16384);
    for (int i=t;i<2048;i+=256){
      int row = i>>5, col = (i&31)*8;
      *(uint4*)(VTs + row*KD_LDP + col) = vg[i];
    }
  }
  uint32_t qa[4][4];
  {
    int r1 = q0 + w*16 + gid, r2 = r1 + 8;
#pragma unroll
    for (int kc=0;kc<4;kc++){
      int c = kc*16 + tid4*2;
      qa[kc][0] = *(const uint32_t*)(g_qb + (size_t)r1*64 + c);
      qa[kc][1] = *(const uint32_t*)(g_qb + (size_t)r2*64 + c);
      qa[kc][2] = *(const uint32_t*)(g_qb + (size_t)r1*64 + c + 8);
      qa[kc][3] = *(const uint32_t*)(g_qb + (size_t)r2*64 + c + 8);
    }
  }
  __syncthreads();
  uint32_t pbr[32][2];
  float rs1 = 0.f, rs2 = 0.f;
#pragma unroll
  for (int ch=0; ch<4; ch++){
    float acc[8][4];
#pragma unroll
    for (int nt=0;nt<8;nt++){ acc[nt][0]=0;acc[nt][1]=0;acc[nt][2]=0;acc[nt][3]=0; }
#pragma unroll
    for (int kc=0;kc<4;kc++){
#pragma unroll
      for (int nt=0;nt<8;nt++){
        int m = ch*64 + nt*8 + gid;
        uint32_t bfr[2];
        bfr[0] = *(const uint32_t*)(Ks + m*KD_LDK + kc*16 + tid4*2);
        bfr[1] = *(const uint32_t*)(Ks + m*KD_LDK + kc*16 + tid4*2 + 8);
        mma16816(acc[nt], qa[kc], bfr, acc[nt]);
      }
    }
#pragma unroll
    for (int nt=0;nt<8;nt++){
      float e0 = __expf(acc[nt][0]);
      float e1 = __expf(acc[nt][1]);
      float e2 = __expf(acc[nt][2]);
      float e3 = __expf(acc[nt][3]);
      rs1 += e0 + e1; rs2 += e2 + e3;
      pbr[ch*8+nt][0] = bf2(e0,e1);
      pbr[ch*8+nt][1] = bf2(e2,e3);
    }
  }
  rs1 = qsum(rs1); rs2 = qsum(rs2);
  float o[8][4];
#pragma unroll
  for (int nt=0;nt<8;nt++){ o[nt][0]=0;o[nt][1]=0;o[nt][2]=0;o[nt][3]=0; }
#pragma unroll
  for (int kc=0;kc<16;kc++){
    int t0 = (kc>>2)*8 + (kc&3)*2;
    uint32_t pa[4];
    pa[0] = pbr[t0][0];
    pa[1] = pbr[t0][1];
    pa[2] = pbr[t0+1][0];
    pa[3] = pbr[t0+1][1];
    int c = kc*16 + tid4*2;
#pragma unroll
    for (int nt=0;nt<8;nt++){
      int vc = nt*8 + gid;
      uint32_t bfr[2];
      bfr[0] = *(const uint32_t*)(VTs + vc*KD_LDP + c);
      bfr[1] = *(const uint32_t*)(VTs + vc*KD_LDP + c + 8);
      mma16816(o[nt], pa, bfr, o[nt]);
    }
  }
  float inv1 = __frcp_rn(rs1), inv2 = __frcp_rn(rs2);
  int r1 = q0 + w*16 + gid, r2 = r1 + 8;
#pragma unroll
  for (int nt=0;nt<8;nt++){
    int col = nt*8 + tid4*2;
    *(float2*)(g_o + (size_t)r1*64 + col) = make_float2(o[nt][0]*inv1, o[nt][1]*inv1);
    *(float2*)(g_o + (size_t)r2*64 + col) = make_float2(o[nt][2]*inv2, o[nt][3]*inv2);
  }
}

// =====================================================================
// kE (HMMA): x_new = x + o@proj_w + pb (-> out), LN2, fc1 -> g_fb (bf16).
// =====================================================================
__global__ void __launch_bounds__(256) kE(const float* __restrict__ x,
    const float* __restrict__ pw, const float* __restrict__ pb,
    const float* __restrict__ l2g, const float* __restrict__ l2b,
    const float* __restrict__ f1w, const float* __restrict__ f1b,
    float* __restrict__ out){
  extern __shared__ __nv_bfloat16 smE_[];
  __nv_bfloat16* pwT = smE_;            // [64][72]   proj_w^T
  __nv_bfloat16* Wt  = pwT + 64*72;     // [256][72]  fc1_w^T
  __nv_bfloat16* h2s = Wt + 256*72;     // 8 x [16][72]
  int t=threadIdx.x, w=t>>5, l=t&31, gid=l>>2, tid4=l&3;
  for (int i=t;i<4096;i+=256){ int k=i>>6, n=i&63; pwT[n*72+k] = __float2bfloat16(pw[i]); }
  for (int i=t;i<16384;i+=256){ int k=i>>8, n=i&255; Wt[n*72+k] = __float2bfloat16(f1w[i]); }
  __syncthreads();
  int r1 = blockIdx.x*128 + w*16 + gid;
  int r2 = r1 + 8;
  uint32_t oa[4][4];
#pragma unroll
  for (int kc=0;kc<4;kc++){
    int c = kc*16 + tid4*2;
    float2 v;
    v = *(const float2*)(g_o + (size_t)r1*64 + c);   oa[kc][0]=bf2(v.x,v.y);
    v = *(const float2*)(g_o + (size_t)r2*64 + c);   oa[kc][1]=bf2(v.x,v.y);
    v = *(const float2*)(g_o + (size_t)r1*64 + c+8); oa[kc][2]=bf2(v.x,v.y);
    v = *(const float2*)(g_o + (size_t)r2*64 + c+8); oa[kc][3]=bf2(v.x,v.y);
  }
  float pr[8][4];
#pragma unroll
  for (int nt=0;nt<8;nt++){ pr[nt][0]=0;pr[nt][1]=0;pr[nt][2]=0;pr[nt][3]=0; }
#pragma unroll
  for (int kc=0;kc<4;kc++)
#pragma unroll
    for (int nt=0;nt<8;nt++){
      uint32_t bfr[2];
      bfr[0] = *(const uint32_t*)(pwT + (nt*8+gid)*72 + kc*16 + tid4*2);
      bfr[1] = *(const uint32_t*)(pwT + (nt*8+gid)*72 + kc*16 + tid4*2 + 8);
      mma16816(pr[nt], oa[kc], bfr, pr[nt]);
    }
  float xn[8][4];
  float s1=0,q1=0,s2=0,q2=0;
#pragma unroll
  for (int nt=0;nt<8;nt++){
    int c0 = nt*8 + tid4*2;
    float2 bias = *(const float2*)(pb + c0);
    float2 x1 = *(const float2*)(x + (size_t)r1*64 + c0);
    float2 x2 = *(const float2*)(x + (size_t)r2*64 + c0);
    xn[nt][0] = x1.x + pr[nt][0] + bias.x;
    xn[nt][1] = x1.y + pr[nt][1] + bias.y;
    xn[nt][2] = x2.x + pr[nt][2] + bias.x;
    xn[nt][3] = x2.y + pr[nt][3] + bias.y;
    *(float2*)(out + (size_t)r1*64 + c0) = make_float2(xn[nt][0], xn[nt][1]);
    *(float2*)(out + (size_t)r2*64 + c0) = make_float2(xn[nt][2], xn[nt][3]);
    s1 += xn[nt][0]+xn[nt][1]; q1 += xn[nt][0]*xn[nt][0]+xn[nt][1]*xn[nt][1];
    s2 += xn[nt][2]+xn[nt][3]; q2 += xn[nt][2]*xn[nt][2]+xn[nt][3]*xn[nt][3];
  }
  s1=qsum(s1); q1=qsum(q1); s2=qsum(s2); q2=qsum(q2);
  float mn1=s1*(1.f/64.f), mn2=s2*(1.f/64.f);
  float iv1=rsqrtf(fmaxf(q1*(1.f/64.f)-mn1*mn1,0.f)+1e-5f);
  float iv2=rsqrtf(fmaxf(q2*(1.f/64.f)-mn2*mn2,0.f)+1e-5f);
  __nv_bfloat16* h2w = h2s + w*16*72;
#pragma unroll
  for (int nt=0;nt<8;nt++){
    int c0 = nt*8 + tid4*2;
    float2 gg = *(const float2*)(l2g + c0);
    float2 bb = *(const float2*)(l2b + c0);
    *(uint32_t*)(h2w + gid*72 + c0)     = bf2((xn[nt][0]-mn1)*iv1*gg.x+bb.x, (xn[nt][1]-mn1)*iv1*gg.y+bb.y);
    *(uint32_t*)(h2w + (gid+8)*72 + c0) = bf2((xn[nt][2]-mn2)*iv2*gg.x+bb.x, (xn[nt][3]-mn2)*iv2*gg.y+bb.y);
  }
  __syncwarp();
  uint32_t ha[4][4];
#pragma unroll
  for (int kc=0;kc<4;kc++){
    int c = kc*16 + tid4*2;
    ha[kc][0] = *(const uint32_t*)(h2w + gid*72 + c);
    ha[kc][1] = *(const uint32_t*)(h2w + (gid+8)*72 + c);
    ha[kc][2] = *(const uint32_t*)(h2w + gid*72 + c + 8);
    ha[kc][3] = *(const uint32_t*)(h2w + (gid+8)*72 + c + 8);
  }
#pragma unroll
  for (int nh=0;nh<2;nh++){
    float acc[16][4];
#pragma unroll
    for (int nt=0;nt<16;nt++){ acc[nt][0]=0;acc[nt][1]=0;acc[nt][2]=0;acc[nt][3]=0; }
#pragma unroll
    for (int kc=0;kc<4;kc++)
#pragma unroll
      for (int nt=0;nt<16;nt++){
        int n = nh*128 + nt*8 + gid;
        uint32_t bfr[2];
        bfr[0] = *(const uint32_t*)(Wt + n*72 + kc*16 + tid4*2);
        bfr[1] = *(const uint32_t*)(Wt + n*72 + kc*16 + tid4*2 + 8);
        mma16816(acc[nt], ha[kc], bfr, acc[nt]);
      }
#pragma unroll
    for (int nt=0;nt<16;nt++){
      int c0 = nh*128 + nt*8 + tid4*2;
      float2 fb = *(const float2*)(f1b + c0);
      *(uint32_t*)(g_fb + (size_t)r1*256 + c0) = bf2(acc[nt][0]+fb.x, acc[nt][1]+fb.y);
      *(uint32_t*)(g_fb + (size_t)r2*256 + c0) = bf2(acc[nt][2]+fb.x, acc[nt][3]+fb.y);
    }
  }
}

// =====================================================================
// kG (HMMA fc2): 3x3 depthwise (SAME, fp32) + exact GELU + fc2 + residual.
// =====================================================================
__global__ void __launch_bounds__(256) kG(const float* __restrict__ dww,
    const float* __restrict__ f2w, const float* __restrict__ f2b,
    float* __restrict__ out){
  extern __shared__ __nv_bfloat16 smG_[];
  __nv_bfloat16* W2T = smG_;             // [64][264]  fc2_w^T
  __nv_bfloat16* fs  = W2T + 64*264;     // [390][72]
  __nv_bfloat16* gsm = fs + 390*72;      // [128][72]
  int t=threadIdx.x, w=t>>5, l=t&31, gid=l>>2, tid4=l&3;
  for (int i=t;i<16384;i+=256){ int k=i>>6, n=i&63; W2T[n*264+k] = __float2bfloat16(f2w[i]); }
  int b = blockIdx.x>>7, y = blockIdx.x&127;
  int chp = t&31;
  int pxb = t>>5;
  float acc[8][4];
#pragma unroll
  for (int nt=0;nt<8;nt++){ acc[nt][0]=0;acc[nt][1]=0;acc[nt][2]=0;acc[nt][3]=0; }
  for (int cc=0;cc<4;cc++){
    int ch0 = cc*64;
    for (int i=t;i<3120;i+=256){
      int r = i>>3, part = i&7;
      int ry = r/130, px = r%130;
      int gy = y-1+ry, gx = px-1;
      uint4 v = make_uint4(0,0,0,0);
      if ((unsigned)gy<128u && (unsigned)gx<128u)
        v = *(const uint4*)(g_fb + ((size_t)((b<<14) + gy*128 + gx))*256 + ch0 + part*8);
      *(uint4*)(fs + r*72 + part*8) = v;
    }
    float2 dwr[9];
#pragma unroll
    for (int kk=0;kk<9;kk++) dwr[kk] = *(const float2*)(dww + kk*256 + ch0 + chp*2);
    __syncthreads();
#pragma unroll
    for (int i=0;i<16;i++){
      int px = pxb + 8*i;
      u64 ga = 0;
#pragma unroll
      for (int ry=0;ry<3;ry++)
#pragma unroll
        for (int kx=0;kx<3;kx++){
          __nv_bfloat162 fv2 = *(const __nv_bfloat162*)(fs + (ry*130 + px + kx)*72 + chp*2);
          float2 fv = __bfloat1622float2(fv2);
          ga = ffma2(pk2(fv.x,fv.y), pk2(dwr[ry*3+kx].x, dwr[ry*3+kx].y), ga);
        }
      float v0,v1; upk2(ga,v0,v1);
      v0 = 0.5f*v0*(1.f + erff(v0*0.70710678118f));
      v1 = 0.5f*v1*(1.f + erff(v1*0.70710678118f));
      *(uint32_t*)(gsm + px*72 + chp*2) = bf2(v0,v1);
    }
    __syncthreads();
#pragma unroll
    for (int kc=0;kc<4;kc++){
      uint32_t pa[4];
      int c = kc*16 + tid4*2;
      pa[0] = *(const uint32_t*)(gsm + (w*16+gid)*72 + c);
      pa[1] = *(const uint32_t*)(gsm + (w*16+gid+8)*72 + c);
      pa[2] = *(const uint32_t*)(gsm + (w*16+gid)*72 + c + 8);
      pa[3] = *(const uint32_t*)(gsm + (w*16+gid+8)*72 + c + 8);
#pragma unroll
      for (int nt=0;nt<8;nt++){
        uint32_t bfr[2];
        bfr[0] = *(const uint32_t*)(W2T + (nt*8+gid)*264 + ch0 + c);
        bfr[1] = *(const uint32_t*)(W2T + (nt*8+gid)*264 + ch0 + c + 8);
        mma16816(acc[nt], pa, bfr, acc[nt]);
      }
    }
  }
  int p1 = w*16 + gid, p2 = p1 + 8;
  size_t base = ((size_t)(b<<14) + y*128);
#pragma unroll
  for (int nt=0;nt<8;nt++){
    int c0 = nt*8 + tid4*2;
    float2 bb = *(const float2*)(f2b + c0);
    float2 ra = *(float2*)(out + (base+p1)*64 + c0);
    float2 rb = *(float2*)(out + (base+p2)*64 + c0);
    *(float2*)(out + (base+p1)*64 + c0) = make_float2(ra.x + acc[nt][0] + bb.x, ra.y + acc[nt][1] + bb.y);
    *(float2*)(out + (base+p2)*64 + c0) = make_float2(rb.x + acc[nt][2] + bb.x, rb.y + acc[nt][3] + bb.y);
  }
}

// =====================================================================
extern "C" void kernel_launch(void* const* d_in, const int* in_sizes, int n_in,
                              void* d_out, int out_size){
  const float* x    = (const float*)d_in[0];
  const float* ln1g = (const float*)d_in[3];
  const float* ln1b = (const float*)d_in[4];
  const float* qw   = (const float*)d_in[5];
  const float* qb   = (const float*)d_in[6];
  const float* kvw  = (const float*)d_in[7];
  const float* kvb  = (const float*)d_in[8];
  const float* pw   = (const float*)d_in[9];
  const float* pb   = (const float*)d_in[10];
  const float* srw  = (const float*)d_in[11];
  const float* srb  = (const float*)d_in[12];
  const float* sng  = (const float*)d_in[13];
  const float* snb  = (const float*)d_in[14];
  const float* l2g  = (const float*)d_in[15];
  const float* l2b  = (const float*)d_in[16];
  const float* f1w  = (const float*)d_in[17];
  const float* f1b  = (const float*)d_in[18];
  const float* dww  = (const float*)d_in[19];
  const float* f2w  = (const float*)d_in[20];
  const float* f2b  = (const float*)d_in[21];
  float* out = (float*)d_out;

  size_t smD = (size_t)(256*KD_LDK + 64*KD_LDP) * sizeof(__nv_bfloat16);   // ~69 KB
  size_t smE = (size_t)(64*72 + 256*72 + 8*16*72) * sizeof(__nv_bfloat16); // ~63 KB
  size_t smG = (size_t)(64*264 + 390*72 + 128*72) * sizeof(__nv_bfloat16); // ~106 KB
  cudaFuncSetAttribute(kD, cudaFuncAttributeMaxDynamicSharedMemorySize, (int)smD);
  cudaFuncSetAttribute(kE, cudaFuncAttributeMaxDynamicSharedMemorySize, (int)smE);
  cudaFuncSetAttribute(kG, cudaFuncAttributeMaxDynamicSharedMemorySize, (int)smG);

  kA<<<1024, 256>>>(x, ln1g, ln1b, qw, qb);
  kB<<<dim3(64,8), 256>>>(srw);
  kC<<<256, 256>>>(srb, sng, snb, kvw, kvb);
  kD<<<1024, 256, smD>>>();
  kE<<<1024, 256, smE>>>(x, pw, pb, l2g, l2b, f1w, f1b, out);
  kG<<<1024, 256, smG>>>(dww, f2w, f2b, out);
}